// round 5
// baseline (speedup 1.0000x reference)
#include <cuda_runtime.h>

#define HWSZ 40000
#define WD 200
#define HD 200

// ---- scratch (allocation-free: __device__ globals) ----
__device__ float g_e    [8 * 64  * HWSZ];   // e after ec1/ec2 stage-in, reused for ag1 out
__device__ float g_e2   [8 * 64  * HWSZ];   // e after ec2 (also ag2 out, 32ch)
__device__ float g_corr [4 * 81  * HWSZ];   // correlation -> softmax weights (in place)
__device__ float g_align[4 * 128 * HWSZ];   // aligned features

// ============================================================================
// conv1x1 (128 -> 64) + bias + relu over cat([src0(4), src1(4)], axis=0)
// grid (625, 8), block 256. Block = 64 oc x 64 px; thread = 4 oc x 4 px.
// ============================================================================
__global__ __launch_bounds__(256) void conv1x1_relu_128_64(
    const float* __restrict__ src0, const float* __restrict__ src1,
    const float* __restrict__ w, const float* __restrict__ bias,
    float* __restrict__ out)
{
    __shared__ __align__(16) float ws[128 * 64];  // [c][oc]
    __shared__ __align__(16) float xs[32 * 64];   // [c_local][px]

    const int n = blockIdx.y;
    const float* src = (n < 4) ? (src0 + (size_t)n * 128 * HWSZ)
                               : (src1 + (size_t)(n - 4) * 128 * HWSZ);
    const int px_base = blockIdx.x * 64;
    const int t = threadIdx.x;

    // weights transposed: ws[c*64+oc] = w[oc*128+c]
    #pragma unroll
    for (int i = 0; i < 32; i++) {
        int idx = t + i * 256;
        int c = idx >> 6, oc = idx & 63;
        ws[idx] = w[oc * 128 + c];
    }

    float acc[4][4];
    #pragma unroll
    for (int i = 0; i < 4; i++)
        #pragma unroll
        for (int j = 0; j < 4; j++) acc[i][j] = 0.f;

    const int oc0 = (t >> 4) * 4;
    const int px0 = (t & 15) * 4;

    for (int c0 = 0; c0 < 128; c0 += 32) {
        __syncthreads();
        #pragma unroll
        for (int i = 0; i < 8; i++) {
            int idx = t + i * 256;
            int c = idx >> 6, px = idx & 63;
            xs[idx] = src[(size_t)(c0 + c) * HWSZ + px_base + px];
        }
        __syncthreads();
        #pragma unroll 8
        for (int c = 0; c < 32; c++) {
            float4 wv = *(const float4*)&ws[(c0 + c) * 64 + oc0];
            float4 xv = *(const float4*)&xs[c * 64 + px0];
            acc[0][0] += wv.x * xv.x; acc[0][1] += wv.x * xv.y;
            acc[0][2] += wv.x * xv.z; acc[0][3] += wv.x * xv.w;
            acc[1][0] += wv.y * xv.x; acc[1][1] += wv.y * xv.y;
            acc[1][2] += wv.y * xv.z; acc[1][3] += wv.y * xv.w;
            acc[2][0] += wv.z * xv.x; acc[2][1] += wv.z * xv.y;
            acc[2][2] += wv.z * xv.z; acc[2][3] += wv.z * xv.w;
            acc[3][0] += wv.w * xv.x; acc[3][1] += wv.w * xv.y;
            acc[3][2] += wv.w * xv.z; acc[3][3] += wv.w * xv.w;
        }
    }

    #pragma unroll
    for (int i = 0; i < 4; i++) {
        int oc = oc0 + i;
        float b = bias[oc];
        float4 r;
        r.x = fmaxf(acc[i][0] + b, 0.f);
        r.y = fmaxf(acc[i][1] + b, 0.f);
        r.z = fmaxf(acc[i][2] + b, 0.f);
        r.w = fmaxf(acc[i][3] + b, 0.f);
        *(float4*)&out[(size_t)(n * 64 + oc) * HWSZ + px_base + px0] = r;
    }
}

// ============================================================================
// conv3x3 (64 -> CO) pad 1 + bias + relu. CO in {64, 32}, 32-oc passes.
// grid (13, 13, 8*CO/32), block 256.
// Block = 16x16 px x 32 oc; thread = 4 px (x-run) x 8 oc.
// ============================================================================
__global__ __launch_bounds__(256) void conv3x3_relu(
    const float* __restrict__ in, const float* __restrict__ w,
    const float* __restrict__ bias, float* __restrict__ out, int CO)
{
    __shared__ __align__(16) float si[16 * 18 * 21];  // [ic][row][col], pitch 21
    __shared__ __align__(16) float sw[16 * 9 * 32];   // [ic][tap][oc]

    const int passes = CO >> 5;
    const int n = blockIdx.z / passes;
    const int pass = blockIdx.z - n * passes;
    const int ocbase = pass * 32;
    const int gy0 = blockIdx.y * 16, gx0 = blockIdx.x * 16;
    const int t = threadIdx.x;
    const int tx = t & 3, ty = (t >> 2) & 15, ocg = t >> 6;
    const int oc0 = ocg * 8;
    const float* inb = in + (size_t)n * 64 * HWSZ;

    float acc[4][8];
    #pragma unroll
    for (int j = 0; j < 4; j++)
        #pragma unroll
        for (int o = 0; o < 8; o++) acc[j][o] = 0.f;

    for (int ic0 = 0; ic0 < 64; ic0 += 16) {
        __syncthreads();
        // input tile with halo (zero pad)
        for (int i = t; i < 16 * 18 * 18; i += 256) {
            int ic = i / 324;
            int rem = i - ic * 324;
            int r = rem / 18, cc = rem - r * 18;
            int gy = gy0 - 1 + r, gx = gx0 - 1 + cc;
            float v = 0.f;
            if (gy >= 0 && gy < HD && gx >= 0 && gx < WD)
                v = inb[(size_t)(ic0 + ic) * HWSZ + gy * WD + gx];
            si[(ic * 18 + r) * 21 + cc] = v;
        }
        // weights chunk: sw[(ic*9 + ki*3 + kj)*32 + oc]
        for (int i = t; i < 16 * 9 * 32; i += 256) {
            int oc = i & 31;
            int rest = i >> 5;                 // ic*9 + ki*3 + kj
            int ic = rest / 9;
            int r2 = rest - ic * 9;
            sw[i] = w[(size_t)(ocbase + oc) * 64 * 9 + (ic0 + ic) * 9 + r2];
        }
        __syncthreads();

        #pragma unroll 1
        for (int ic = 0; ic < 16; ic++) {
            #pragma unroll
            for (int ki = 0; ki < 3; ki++) {
                const float* xr = &si[(ic * 18 + ty + ki) * 21 + tx * 4];
                float xw[6];
                #pragma unroll
                for (int i2 = 0; i2 < 6; i2++) xw[i2] = xr[i2];
                #pragma unroll
                for (int kj = 0; kj < 3; kj++) {
                    const float* wp = &sw[(ic * 9 + ki * 3 + kj) * 32 + oc0];
                    float4 wa = *(const float4*)wp;
                    float4 wb = *(const float4*)(wp + 4);
                    #pragma unroll
                    for (int j = 0; j < 4; j++) {
                        float xv = xw[j + kj];
                        acc[j][0] += xv * wa.x; acc[j][1] += xv * wa.y;
                        acc[j][2] += xv * wa.z; acc[j][3] += xv * wa.w;
                        acc[j][4] += xv * wb.x; acc[j][5] += xv * wb.y;
                        acc[j][6] += xv * wb.z; acc[j][7] += xv * wb.w;
                    }
                }
            }
        }
    }

    const int gy = gy0 + ty;
    if (gy < HD) {
        #pragma unroll
        for (int j = 0; j < 4; j++) {
            int gx = gx0 + tx * 4 + j;
            if (gx < WD) {
                #pragma unroll
                for (int o = 0; o < 8; o++) {
                    int oc = ocbase + oc0 + o;
                    float v = acc[j][o] + bias[oc];
                    out[(size_t)(n * CO + oc) * HWSZ + gy * WD + gx] = v > 0.f ? v : 0.f;
                }
            }
        }
    }
}

// ============================================================================
// correlation: corr[n][di*9+dj][p] = sum_c e_sel[c][p] * e_cur[c][p + off]
// grid (40, 9, 4), block 256; thread = 4 consecutive px (quads never wrap rows).
// ============================================================================
__global__ __launch_bounds__(256) void corr_kernel(
    const float* __restrict__ e, float* __restrict__ corr)
{
    const int n = blockIdx.z, di = blockIdx.y;
    const int q = blockIdx.x * 256 + threadIdx.x;
    if (q >= 10000) return;
    const int p0 = q * 4;
    const int y = p0 / WD, x0 = p0 - y * WD;
    const float* sel = e + (size_t)n * 64 * HWSZ;
    const float* cur = e + (size_t)(n + 4) * 64 * HWSZ;

    float acc[9][4];
    #pragma unroll
    for (int dj = 0; dj < 9; dj++)
        #pragma unroll
        for (int j = 0; j < 4; j++) acc[dj][j] = 0.f;

    const int yy = y + di - 4;
    if (yy >= 0 && yy < HD) {
        #pragma unroll 1
        for (int c = 0; c < 64; c++) {
            float4 s = *(const float4*)&sel[(size_t)c * HWSZ + p0];
            const float* crow = &cur[(size_t)c * HWSZ + yy * WD];
            float win[12];
            #pragma unroll
            for (int i = 0; i < 12; i++) {
                int xx = x0 - 4 + i;
                win[i] = (xx >= 0 && xx < WD) ? crow[xx] : 0.f;
            }
            #pragma unroll
            for (int dj = 0; dj < 9; dj++) {
                acc[dj][0] += s.x * win[dj];
                acc[dj][1] += s.y * win[dj + 1];
                acc[dj][2] += s.z * win[dj + 2];
                acc[dj][3] += s.w * win[dj + 3];
            }
        }
    }
    #pragma unroll
    for (int dj = 0; dj < 9; dj++) {
        float4 r = {acc[dj][0], acc[dj][1], acc[dj][2], acc[dj][3]};
        *(float4*)&corr[(size_t)(n * 81 + di * 9 + dj) * HWSZ + p0] = r;
    }
}

// ============================================================================
// softmax over k=81, in place. thread = 4 px. grid 157, block 256.
// ============================================================================
__global__ __launch_bounds__(256) void softmax81(float* __restrict__ c)
{
    const int tid = blockIdx.x * 256 + threadIdx.x;
    if (tid >= 40000) return;
    const int n = tid / 10000, q = tid - n * 10000;
    float* base = c + (size_t)n * 81 * HWSZ + q * 4;

    float4 m = *(const float4*)base;
    for (int k = 1; k < 81; k++) {
        float4 v = *(const float4*)(base + (size_t)k * HWSZ);
        m.x = fmaxf(m.x, v.x); m.y = fmaxf(m.y, v.y);
        m.z = fmaxf(m.z, v.z); m.w = fmaxf(m.w, v.w);
    }
    float4 s = {0.f, 0.f, 0.f, 0.f};
    for (int k = 0; k < 81; k++) {
        float4 v = *(const float4*)(base + (size_t)k * HWSZ);
        s.x += __expf(v.x - m.x); s.y += __expf(v.y - m.y);
        s.z += __expf(v.z - m.z); s.w += __expf(v.w - m.w);
    }
    float4 inv = {1.f / s.x, 1.f / s.y, 1.f / s.z, 1.f / s.w};
    for (int k = 0; k < 81; k++) {
        float* p = base + (size_t)k * HWSZ;
        float4 v = *(const float4*)p;
        float4 r;
        r.x = __expf(v.x - m.x) * inv.x;
        r.y = __expf(v.y - m.y) * inv.y;
        r.z = __expf(v.z - m.z) * inv.z;
        r.w = __expf(v.w - m.w) * inv.w;
        *(float4*)p = r;
    }
}

// ============================================================================
// align[n][c][p] = sum_k w[n][k][p] * sel[n][c][p + off_k]
// grid (157, 4 cpass, 4 n), block 256 = 64 quads x 4 c-groups (8c each).
// ============================================================================
__global__ __launch_bounds__(256) void align_kernel(
    const float* __restrict__ wgt, const float* __restrict__ fsel,
    float* __restrict__ outp)
{
    __shared__ __align__(16) float ws[9 * 256];  // [dj][px in block]

    const int n = blockIdx.z, cpass = blockIdx.y;
    const int t = threadIdx.x;
    const int ql = t & 63, cg = t >> 6;
    const int qb = blockIdx.x * 64;
    const int q = qb + ql;
    const bool active = q < 10000;
    const int p0 = q * 4;
    const int y = p0 / WD, x0 = p0 - y * WD;
    const int c0 = cpass * 32 + cg * 8;
    const float* sel = fsel + (size_t)n * 128 * HWSZ;
    const int pxbase = qb * 4;

    float acc[8][4];
    #pragma unroll
    for (int ci = 0; ci < 8; ci++)
        #pragma unroll
        for (int j = 0; j < 4; j++) acc[ci][j] = 0.f;

    for (int di = 0; di < 9; di++) {
        __syncthreads();
        #pragma unroll
        for (int i2 = 0; i2 < 9; i2++) {
            int i = t + i2 * 256;
            int dj = i >> 8, col = i & 255;
            int idx = pxbase + col;
            ws[i] = (idx < HWSZ) ? wgt[(size_t)(n * 81 + di * 9 + dj) * HWSZ + idx] : 0.f;
        }
        __syncthreads();

        const int yy = y + di - 4;
        if (active && yy >= 0 && yy < HD) {
            float4 wv[9];
            #pragma unroll
            for (int dj = 0; dj < 9; dj++)
                wv[dj] = *(const float4*)&ws[dj * 256 + ql * 4];
            #pragma unroll
            for (int ci = 0; ci < 8; ci++) {
                const float* srow = sel + (size_t)(c0 + ci) * HWSZ + yy * WD;
                float win[12];
                #pragma unroll
                for (int i2 = 0; i2 < 12; i2++) {
                    int xx = x0 - 4 + i2;
                    win[i2] = (xx >= 0 && xx < WD) ? srow[xx] : 0.f;
                }
                #pragma unroll
                for (int dj = 0; dj < 9; dj++) {
                    acc[ci][0] += wv[dj].x * win[dj];
                    acc[ci][1] += wv[dj].y * win[dj + 1];
                    acc[ci][2] += wv[dj].z * win[dj + 2];
                    acc[ci][3] += wv[dj].w * win[dj + 3];
                }
            }
        }
    }

    if (active) {
        #pragma unroll
        for (int ci = 0; ci < 8; ci++) {
            float4 r = {acc[ci][0], acc[ci][1], acc[ci][2], acc[ci][3]};
            *(float4*)&outp[(size_t)(n * 128 + c0 + ci) * HWSZ + p0] = r;
        }
    }
}

// ============================================================================
// ag3 1x1 (32->1) + relu, 2-way softmax, final blend. thread = 4 px.
// ============================================================================
__global__ __launch_bounds__(256) void final_blend(
    const float* __restrict__ a2, const float* __restrict__ alg,
    const float* __restrict__ fcur, const float* __restrict__ w3,
    const float* __restrict__ b3, float* __restrict__ out)
{
    const int tid = blockIdx.x * 256 + threadIdx.x;
    if (tid >= 40000) return;
    const int n = tid / 10000, q = tid - n * 10000;
    const int p0 = q * 4;

    float4 z0 = {0.f, 0.f, 0.f, 0.f}, z1 = {0.f, 0.f, 0.f, 0.f};
    #pragma unroll 4
    for (int c = 0; c < 32; c++) {
        float wc = w3[c];
        float4 va = *(const float4*)&a2[(size_t)(n * 32 + c) * HWSZ + p0];
        float4 vb = *(const float4*)&a2[(size_t)((n + 4) * 32 + c) * HWSZ + p0];
        z0.x += wc * va.x; z0.y += wc * va.y; z0.z += wc * va.z; z0.w += wc * va.w;
        z1.x += wc * vb.x; z1.y += wc * vb.y; z1.z += wc * vb.z; z1.w += wc * vb.w;
    }
    const float b = b3[0];
    z0.x = fmaxf(z0.x + b, 0.f); z0.y = fmaxf(z0.y + b, 0.f);
    z0.z = fmaxf(z0.z + b, 0.f); z0.w = fmaxf(z0.w + b, 0.f);
    z1.x = fmaxf(z1.x + b, 0.f); z1.y = fmaxf(z1.y + b, 0.f);
    z1.z = fmaxf(z1.z + b, 0.f); z1.w = fmaxf(z1.w + b, 0.f);

    float4 w0;
    w0.x = 1.f / (1.f + __expf(z1.x - z0.x));
    w0.y = 1.f / (1.f + __expf(z1.y - z0.y));
    w0.z = 1.f / (1.f + __expf(z1.z - z0.z));
    w0.w = 1.f / (1.f + __expf(z1.w - z0.w));

    #pragma unroll 4
    for (int c = 0; c < 128; c++) {
        float4 va = *(const float4*)&alg[(size_t)(n * 128 + c) * HWSZ + p0];
        float4 vc = *(const float4*)&fcur[(size_t)(n * 128 + c) * HWSZ + p0];
        float4 r;
        r.x = w0.x * va.x + (1.f - w0.x) * vc.x;
        r.y = w0.y * va.y + (1.f - w0.y) * vc.y;
        r.z = w0.z * va.z + (1.f - w0.z) * vc.z;
        r.w = w0.w * va.w + (1.f - w0.w) * vc.w;
        *(float4*)&out[(size_t)(n * 128 + c) * HWSZ + p0] = r;
    }
}

// ============================================================================
extern "C" void kernel_launch(void* const* d_in, const int* in_sizes, int n_in,
                              void* d_out, int out_size)
{
    (void)in_sizes; (void)n_in; (void)out_size;
    const float* fsel  = (const float*)d_in[0];
    const float* fcur  = (const float*)d_in[1];
    const float* ec1_w = (const float*)d_in[2];
    const float* ec1_b = (const float*)d_in[3];
    const float* ec2_w = (const float*)d_in[4];
    const float* ec2_b = (const float*)d_in[5];
    const float* ag1_w = (const float*)d_in[6];
    const float* ag1_b = (const float*)d_in[7];
    const float* ag2_w = (const float*)d_in[8];
    const float* ag2_b = (const float*)d_in[9];
    const float* ag3_w = (const float*)d_in[10];
    const float* ag3_b = (const float*)d_in[11];
    float* out = (float*)d_out;

    float *pe, *pe2, *pcorr, *palign;
    cudaGetSymbolAddress((void**)&pe,     g_e);
    cudaGetSymbolAddress((void**)&pe2,    g_e2);
    cudaGetSymbolAddress((void**)&pcorr,  g_corr);
    cudaGetSymbolAddress((void**)&palign, g_align);

    // e = relu(ec2(relu(ec1(cat(sel, cur)))))
    conv1x1_relu_128_64<<<dim3(625, 8), 256>>>(fsel, fcur, ec1_w, ec1_b, pe);
    conv3x3_relu<<<dim3(13, 13, 16), 256>>>(pe, ec2_w, ec2_b, pe2, 64);
    // corr + softmax weights
    corr_kernel<<<dim3(40, 9, 4), 256>>>(pe2, pcorr);
    softmax81<<<157, 256>>>(pcorr);
    // aligned features
    align_kernel<<<dim3(157, 4, 4), 256>>>(pcorr, fsel, palign);
    // aggregation branch
    conv1x1_relu_128_64<<<dim3(625, 8), 256>>>(palign, fcur, ag1_w, ag1_b, pe);
    conv3x3_relu<<<dim3(13, 13, 8), 256>>>(pe, ag2_w, ag2_b, pe2, 32);
    final_blend<<<157, 256>>>(pe2, palign, fcur, ag3_w, ag3_b, out);
}